// round 4
// baseline (speedup 1.0000x reference)
#include <cuda_runtime.h>
#include <cuda_bf16.h>
#include <cstdint>

#define LRELU_ALPHA 0.2f

constexpr int N    = 8192;
constexpr int KIN  = 512;
constexpr int OUTD = 256;
constexpr int W257 = OUTD + 1;
constexpr int NCH  = 1024;
constexpr int CHL  = N / NCH;    // 8

// ---------------- scratch (device globals; no allocation) ----------------
__device__ float g_h[N * OUTD];
__device__ float g_s2[N];
__device__ float g_key[N];
__device__ int   g_idx[N];
__device__ float g_cs1[NCH * W257];
__device__ float g_cs2[NCH * W257];
__device__ float g_co1[NCH * W257];
__device__ float g_co2[NCH * W257];
__device__ float g_SE[(N + 1) * W257];
__device__ float g_P2[(N + 1) * W257];

__device__ __nv_bfloat16 g_xh[N * KIN];
__device__ __nv_bfloat16 g_xl[N * KIN];
__device__ __nv_bfloat16 g_wh[OUTD * KIN];
__device__ __nv_bfloat16 g_wl[OUTD * KIN];

__device__ __forceinline__ uint32_t smem_u32(const void* p) {
    uint32_t a;
    asm("{ .reg .u64 t; cvta.to.shared.u64 t, %1; cvt.u32.u64 %0, t; }" : "=r"(a) : "l"(p));
    return a;
}

// ==================== convert fp32 -> bf16 hi/lo ====================
__global__ void convert_kernel(const float* __restrict__ x, const float* __restrict__ Wm) {
    int i = blockIdx.x * blockDim.x + threadIdx.x;
    constexpr int XT = N * KIN / 2;
    constexpr int WT = OUTD * KIN / 2;
    if (i < XT) {
        float2 v = ((const float2*)x)[i];
        __nv_bfloat16 h0 = __float2bfloat16(v.x), h1 = __float2bfloat16(v.y);
        __nv_bfloat16 l0 = __float2bfloat16(v.x - __bfloat162float(h0));
        __nv_bfloat16 l1 = __float2bfloat16(v.y - __bfloat162float(h1));
        ((__nv_bfloat162*)g_xh)[i] = __nv_bfloat162(h0, h1);
        ((__nv_bfloat162*)g_xl)[i] = __nv_bfloat162(l0, l1);
    } else if (i < XT + WT) {
        int j = i - XT;
        float2 v = ((const float2*)Wm)[j];
        __nv_bfloat16 h0 = __float2bfloat16(v.x), h1 = __float2bfloat16(v.y);
        __nv_bfloat16 l0 = __float2bfloat16(v.x - __bfloat162float(h0));
        __nv_bfloat16 l1 = __float2bfloat16(v.y - __bfloat162float(h1));
        ((__nv_bfloat162*)g_wh)[j] = __nv_bfloat162(h0, h1);
        ((__nv_bfloat162*)g_wl)[j] = __nv_bfloat162(l0, l1);
    }
}

// ==================== bf16 mma.sync GEMM: h = x @ W^T ====================
constexpr int SSTR = 40;

__device__ __forceinline__ void ldsm_x4(uint32_t (&r)[4], uint32_t addr) {
    asm volatile("ldmatrix.sync.aligned.m8n8.x4.shared.b16 {%0,%1,%2,%3}, [%4];"
                 : "=r"(r[0]), "=r"(r[1]), "=r"(r[2]), "=r"(r[3]) : "r"(addr));
}
__device__ __forceinline__ void mma_bf16(float (&c)[4], const uint32_t (&a)[4],
                                         uint32_t b0, uint32_t b1) {
    asm volatile(
        "mma.sync.aligned.m16n8k16.row.col.f32.bf16.bf16.f32 "
        "{%0,%1,%2,%3}, {%4,%5,%6,%7}, {%8,%9}, {%0,%1,%2,%3};"
        : "+f"(c[0]), "+f"(c[1]), "+f"(c[2]), "+f"(c[3])
        : "r"(a[0]), "r"(a[1]), "r"(a[2]), "r"(a[3]), "r"(b0), "r"(b1));
}

__global__ void __launch_bounds__(256, 1) gemm_tc_kernel() {
    __shared__ __nv_bfloat16 sAh[128 * SSTR];
    __shared__ __nv_bfloat16 sAl[128 * SSTR];
    __shared__ __nv_bfloat16 sBh[128 * SSTR];
    __shared__ __nv_bfloat16 sBl[128 * SSTR];

    const int tid  = threadIdx.x;
    const int wid  = tid >> 5;
    const int lane = tid & 31;
    const int wm   = wid & 1;
    const int wn   = wid >> 1;
    const int m0   = blockIdx.y * 128;
    const int n0   = blockIdx.x * 128;

    const uint32_t bAh = smem_u32(sAh);
    const uint32_t bAl = smem_u32(sAl);
    const uint32_t bBh = smem_u32(sBh);
    const uint32_t bBl = smem_u32(sBl);

    float acc[4][4][4] = {};

    for (int kc = 0; kc < KIN / 32; ++kc) {
        #pragma unroll
        for (int i = 0; i < 2; ++i) {
            int lin = i * 256 + tid;
            int r = lin >> 2, c4 = lin & 3;
            size_t go = (size_t)r * KIN + kc * 32 + c4 * 8;
            int so = r * SSTR + c4 * 8;
            *(uint4*)(sAh + so) = *(const uint4*)(g_xh + (size_t)m0 * KIN + go);
            *(uint4*)(sAl + so) = *(const uint4*)(g_xl + (size_t)m0 * KIN + go);
            *(uint4*)(sBh + so) = *(const uint4*)(g_wh + (size_t)n0 * KIN + go);
            *(uint4*)(sBl + so) = *(const uint4*)(g_wl + (size_t)n0 * KIN + go);
        }
        __syncthreads();

        #pragma unroll
        for (int kk = 0; kk < 2; ++kk) {
            uint32_t ah[4][4], al[4][4], bh[2][4], bl[2][4];
            #pragma unroll
            for (int mt = 0; mt < 4; ++mt) {
                uint32_t off = (uint32_t)((wm * 64 + mt * 16 + (lane & 15)) * SSTR
                                          + kk * 16 + (lane >> 4) * 8) * 2;
                ldsm_x4(ah[mt], bAh + off);
                ldsm_x4(al[mt], bAl + off);
            }
            #pragma unroll
            for (int ntp = 0; ntp < 2; ++ntp) {
                uint32_t off = (uint32_t)((wn * 32 + ntp * 16 + ((lane >> 4) * 8) + (lane & 7)) * SSTR
                                          + kk * 16 + ((lane >> 3) & 1) * 8) * 2;
                ldsm_x4(bh[ntp], bBh + off);
                ldsm_x4(bl[ntp], bBl + off);
            }
            #pragma unroll
            for (int mt = 0; mt < 4; ++mt)
                #pragma unroll
                for (int nf = 0; nf < 4; ++nf) {
                    uint32_t bh0 = bh[nf >> 1][(nf & 1) * 2], bh1 = bh[nf >> 1][(nf & 1) * 2 + 1];
                    uint32_t bl0 = bl[nf >> 1][(nf & 1) * 2], bl1 = bl[nf >> 1][(nf & 1) * 2 + 1];
                    mma_bf16(acc[mt][nf], ah[mt], bh0, bh1);
                    mma_bf16(acc[mt][nf], ah[mt], bl0, bl1);
                    mma_bf16(acc[mt][nf], al[mt], bh0, bh1);
                }
        }
        __syncthreads();
    }

    #pragma unroll
    for (int mt = 0; mt < 4; ++mt)
        #pragma unroll
        for (int nf = 0; nf < 4; ++nf) {
            int row0 = m0 + wm * 64 + mt * 16 + (lane >> 2);
            int col  = n0 + wn * 32 + nf * 8 + (lane & 3) * 2;
            *(float2*)&g_h[(size_t)row0 * OUTD + col] =
                make_float2(acc[mt][nf][0], acc[mt][nf][1]);
            *(float2*)&g_h[(size_t)(row0 + 8) * OUTD + col] =
                make_float2(acc[mt][nf][2], acc[mt][nf][3]);
        }
}

// ==================== s1, s2 ====================
__global__ void s12_kernel(const float* __restrict__ a1, const float* __restrict__ a2) {
    int i = blockIdx.x;
    int k = threadIdx.x;
    float h = g_h[(size_t)i * OUTD + k];
    float v1 = h * a1[k];
    float v2 = h * a2[k];
    #pragma unroll
    for (int o = 16; o; o >>= 1) {
        v1 += __shfl_down_sync(0xFFFFFFFFu, v1, o);
        v2 += __shfl_down_sync(0xFFFFFFFFu, v2, o);
    }
    __shared__ float r1[8], r2[8];
    if ((k & 31) == 0) { r1[k >> 5] = v1; r2[k >> 5] = v2; }
    __syncthreads();
    if (k < 8) {
        v1 = r1[k]; v2 = r2[k];
        #pragma unroll
        for (int o = 4; o; o >>= 1) {
            v1 += __shfl_down_sync(0xFFu, v1, o);
            v2 += __shfl_down_sync(0xFFu, v2, o);
        }
        if (k == 0) { g_key[i] = v1; g_s2[i] = v2; }
    }
}

// ==================== bitonic sort: shuffle-based within-warp stages ====================
#define CE(i, j, up) { if ((v[i] > v[j]) == (up)) { unsigned long long t = v[i]; v[i] = v[j]; v[j] = t; } }

__device__ __forceinline__ void shfl_stage(unsigned long long (&v)[8], int d, bool up, int tid) {
    bool keep_min = (((tid & d) == 0) == up);
    #pragma unroll
    for (int i = 0; i < 8; ++i) {
        unsigned long long p = __shfl_xor_sync(0xFFFFFFFFu, v[i], d);
        unsigned long long mn = v[i] < p ? v[i] : p;
        unsigned long long mx = v[i] < p ? p : v[i];
        v[i] = keep_min ? mn : mx;
    }
}
__device__ __forceinline__ void reg_tail(unsigned long long (&v)[8], bool up) {
    CE(0,4,up) CE(1,5,up) CE(2,6,up) CE(3,7,up)
    CE(0,2,up) CE(1,3,up) CE(4,6,up) CE(5,7,up)
    CE(0,1,up) CE(2,3,up) CE(4,5,up) CE(6,7,up)
}

__global__ void sort_kernel() {
    extern __shared__ unsigned long long s[];   // 8192 * 8B = 64KB
    const int tid = threadIdx.x;
    const int base = tid * 8;

    unsigned long long v[8];
    #pragma unroll
    for (int i = 0; i < 8; ++i) {
        uint32_t u = __float_as_uint(g_key[base + i]);
        u ^= (u & 0x80000000u) ? 0xFFFFFFFFu : 0x80000000u;
        v[i] = ((unsigned long long)u << 13) | (unsigned)(base + i);
    }

    // sizes 2,4,8: in-thread
    CE(0,1,true) CE(2,3,false) CE(4,5,true) CE(6,7,false)
    CE(0,2,true) CE(1,3,true)  CE(4,6,false) CE(5,7,false)
    CE(0,1,true) CE(2,3,true)  CE(4,5,false) CE(6,7,false)
    {
        bool up8 = ((base & 8) == 0);
        reg_tail(v, up8);
    }

    // sizes 16..256: shuffle + register, no smem
    #pragma unroll
    for (int size = 16; size <= 256; size <<= 1) {
        bool up = ((base & size) == 0);
        #pragma unroll
        for (int stride = size >> 1; stride >= 8; stride >>= 1)
            shfl_stage(v, stride >> 3, up, tid);
        reg_tail(v, up);
    }

    #pragma unroll
    for (int i = 0; i < 8; ++i) s[base + i] = v[i];
    __syncthreads();

    // sizes 512..8192: smem for strides >= 256, shuffles/registers below
    for (int size = 512; size <= N; size <<= 1) {
        for (int stride = size >> 1; stride >= 256; stride >>= 1) {
            #pragma unroll
            for (int t = 0; t < N / 2; t += 1024) {
                int i = t + tid;
                int a = ((i & ~(stride - 1)) << 1) | (i & (stride - 1));
                int b = a + stride;
                bool up = ((a & size) == 0);
                unsigned long long x = s[a], y = s[b];
                if ((x > y) == up) { s[a] = y; s[b] = x; }
            }
            __syncthreads();
        }
        #pragma unroll
        for (int i = 0; i < 8; ++i) v[i] = s[base + i];
        bool up = ((base & size) == 0);
        shfl_stage(v, 16, up, tid);
        shfl_stage(v, 8,  up, tid);
        shfl_stage(v, 4,  up, tid);
        shfl_stage(v, 2,  up, tid);
        shfl_stage(v, 1,  up, tid);
        reg_tail(v, up);
        #pragma unroll
        for (int i = 0; i < 8; ++i) s[base + i] = v[i];
        __syncthreads();
    }

    #pragma unroll
    for (int i = 0; i < 8; ++i) {
        unsigned long long p = s[base + i];
        int idx = (int)(p & 0x1FFFu);
        uint32_t u = (uint32_t)(p >> 13);
        u ^= (u & 0x80000000u) ? 0x80000000u : 0xFFFFFFFFu;
        g_key[base + i] = __uint_as_float(u);
        g_idx[base + i] = idx;
    }
}

// ==================== pass 1: per-chunk weighted sums ====================
__global__ void chunksum_kernel() {
    int c = blockIdx.x;
    int k = threadIdx.x;
    if (k >= W257) return;
    float m1 = g_key[N - 1];
    float acc1 = 0.f, acc2 = 0.f;
    #pragma unroll
    for (int r = 0; r < CHL; ++r) {
        int p = c * CHL + r;
        float d = g_key[p] - m1;
        float w1 = __expf(d);
        float w2 = __expf(LRELU_ALPHA * d);
        float v = (k < OUTD) ? g_h[(size_t)g_idx[p] * OUTD + k] : 1.0f;
        acc1 += w1 * v;
        acc2 += w2 * v;
    }
    g_cs1[c * W257 + k] = acc1;
    g_cs2[c * W257 + k] = acc2;
}

// ==================== pass 2: chunk-offset scans ====================
__global__ void chunkscan_kernel() {
    int k = threadIdx.x;
    if (k >= W257) return;
    float off = 0.f;
    #pragma unroll 4
    for (int c = 0; c < NCH; ++c) {
        g_co2[c * W257 + k] = off;
        off += g_cs2[c * W257 + k];
    }
    off = 0.f;
    #pragma unroll 4
    for (int c = NCH - 1; c >= 0; --c) {
        g_co1[c * W257 + k] = off;
        off += g_cs1[c * W257 + k];
    }
}

// ==================== pass 3: full prefix/suffix arrays ====================
__global__ void writescan_kernel() {
    int c = blockIdx.x;
    int k = threadIdx.x;
    if (k >= W257) return;
    float m1 = g_key[N - 1];

    float acc = g_co2[c * W257 + k];
    #pragma unroll
    for (int r = 0; r < CHL; ++r) {
        int p = c * CHL + r;
        g_P2[(size_t)p * W257 + k] = acc;
        float v = (k < OUTD) ? g_h[(size_t)g_idx[p] * OUTD + k] : 1.0f;
        acc += __expf(LRELU_ALPHA * (g_key[p] - m1)) * v;
    }
    if (c == NCH - 1) g_P2[(size_t)N * W257 + k] = acc;

    acc = g_co1[c * W257 + k];
    #pragma unroll
    for (int r = CHL - 1; r >= 0; --r) {
        int p = c * CHL + r;
        float v = (k < OUTD) ? g_h[(size_t)g_idx[p] * OUTD + k] : 1.0f;
        acc += __expf(g_key[p] - m1) * v;
        g_SE[(size_t)p * W257 + k] = acc;
    }
    if (c == NCH - 1) g_SE[(size_t)N * W257 + k] = 0.f;
}

// ==================== epilogue ====================
__global__ void out_kernel(float* __restrict__ out) {
    int i = blockIdx.x;
    int k = threadIdx.x;
    __shared__ int   sp;
    __shared__ float sr;
    if (k == 0) {
        float m1 = g_key[N - 1];
        float s2 = g_s2[i];
        float t = -s2;
        int lo = 0, hi = N;
        while (lo < hi) {
            int mid = (lo + hi) >> 1;
            if (g_key[mid] > t) hi = mid; else lo = mid + 1;
        }
        sp = lo;
        sr = __expf((LRELU_ALPHA - 1.0f) * (s2 + m1));
    }
    __syncthreads();
    size_t basep = (size_t)sp * W257;
    float r = sr;
    float den = g_SE[basep + OUTD] + r * g_P2[basep + OUTD];
    float num = g_SE[basep + k]    + r * g_P2[basep + k];
    out[(size_t)i * OUTD + k] = num / den;
}

// ==================== launch ====================
extern "C" void kernel_launch(void* const* d_in, const int* in_sizes, int n_in,
                              void* d_out, int out_size) {
    const float* x  = (const float*)d_in[0];
    const float* Wm = (const float*)d_in[2];
    const float* a1 = (const float*)d_in[3];
    const float* a2 = (const float*)d_in[4];
    float* out = (float*)d_out;

    int pairs = (N * KIN + OUTD * KIN) / 2;
    convert_kernel<<<(pairs + 255) / 256, 256>>>(x, Wm);

    gemm_tc_kernel<<<dim3(OUTD / 128, N / 128), 256>>>();

    s12_kernel<<<N, 256>>>(a1, a2);

    cudaFuncSetAttribute(sort_kernel, cudaFuncAttributeMaxDynamicSharedMemorySize, 65536);
    sort_kernel<<<1, 1024, 65536>>>();

    chunksum_kernel<<<NCH, 288>>>();
    chunkscan_kernel<<<1, 288>>>();
    writescan_kernel<<<NCH, 288>>>();
    out_kernel<<<N, 256>>>(out);
}

// round 5
// speedup vs baseline: 6.7253x; 6.7253x over previous
#include <cuda_runtime.h>
#include <cuda_bf16.h>
#include <cstdint>

#define LRELU_ALPHA 0.2f

constexpr int N    = 8192;
constexpr int KIN  = 512;
constexpr int OUTD = 256;
constexpr int W257 = OUTD + 1;
constexpr int NCH  = 512;
constexpr int CHL  = N / NCH;    // 16

// ---------------- scratch (device globals; no allocation) ----------------
__device__ float g_h[N * OUTD];
__device__ float g_s2[N];
__device__ float g_key[N];
__device__ int   g_idx[N];
__device__ float g_cs1[W257 * NCH];     // transposed: [k][c]
__device__ float g_cs2[W257 * NCH];
__device__ float g_co1[W257 * NCH];
__device__ float g_co2[W257 * NCH];
__device__ float g_SE[(N + 1) * W257];
__device__ float g_P2[(N + 1) * W257];

__device__ __nv_bfloat16 g_xh[N * KIN];
__device__ __nv_bfloat16 g_xl[N * KIN];
__device__ __nv_bfloat16 g_wh[OUTD * KIN];
__device__ __nv_bfloat16 g_wl[OUTD * KIN];

__device__ __forceinline__ uint32_t smem_u32(const void* p) {
    uint32_t a;
    asm("{ .reg .u64 t; cvta.to.shared.u64 t, %1; cvt.u32.u64 %0, t; }" : "=r"(a) : "l"(p));
    return a;
}

// ==================== convert fp32 -> bf16 hi/lo ====================
__global__ void convert_kernel(const float* __restrict__ x, const float* __restrict__ Wm) {
    int i = blockIdx.x * blockDim.x + threadIdx.x;
    constexpr int XT = N * KIN / 2;
    constexpr int WT = OUTD * KIN / 2;
    if (i < XT) {
        float2 v = ((const float2*)x)[i];
        __nv_bfloat16 h0 = __float2bfloat16(v.x), h1 = __float2bfloat16(v.y);
        __nv_bfloat16 l0 = __float2bfloat16(v.x - __bfloat162float(h0));
        __nv_bfloat16 l1 = __float2bfloat16(v.y - __bfloat162float(h1));
        ((__nv_bfloat162*)g_xh)[i] = __nv_bfloat162(h0, h1);
        ((__nv_bfloat162*)g_xl)[i] = __nv_bfloat162(l0, l1);
    } else if (i < XT + WT) {
        int j = i - XT;
        float2 v = ((const float2*)Wm)[j];
        __nv_bfloat16 h0 = __float2bfloat16(v.x), h1 = __float2bfloat16(v.y);
        __nv_bfloat16 l0 = __float2bfloat16(v.x - __bfloat162float(h0));
        __nv_bfloat16 l1 = __float2bfloat16(v.y - __bfloat162float(h1));
        ((__nv_bfloat162*)g_wh)[j] = __nv_bfloat162(h0, h1);
        ((__nv_bfloat162*)g_wl)[j] = __nv_bfloat162(l0, l1);
    }
}

// ==================== bf16 mma.sync GEMM: h = x @ W^T ====================
constexpr int SSTR = 40;

__device__ __forceinline__ void ldsm_x4(uint32_t (&r)[4], uint32_t addr) {
    asm volatile("ldmatrix.sync.aligned.m8n8.x4.shared.b16 {%0,%1,%2,%3}, [%4];"
                 : "=r"(r[0]), "=r"(r[1]), "=r"(r[2]), "=r"(r[3]) : "r"(addr));
}
__device__ __forceinline__ void mma_bf16(float (&c)[4], const uint32_t (&a)[4],
                                         uint32_t b0, uint32_t b1) {
    asm volatile(
        "mma.sync.aligned.m16n8k16.row.col.f32.bf16.bf16.f32 "
        "{%0,%1,%2,%3}, {%4,%5,%6,%7}, {%8,%9}, {%0,%1,%2,%3};"
        : "+f"(c[0]), "+f"(c[1]), "+f"(c[2]), "+f"(c[3])
        : "r"(a[0]), "r"(a[1]), "r"(a[2]), "r"(a[3]), "r"(b0), "r"(b1));
}

__global__ void __launch_bounds__(256, 1) gemm_tc_kernel() {
    __shared__ __nv_bfloat16 sAh[128 * SSTR];
    __shared__ __nv_bfloat16 sAl[128 * SSTR];
    __shared__ __nv_bfloat16 sBh[128 * SSTR];
    __shared__ __nv_bfloat16 sBl[128 * SSTR];

    const int tid  = threadIdx.x;
    const int wid  = tid >> 5;
    const int lane = tid & 31;
    const int wm   = wid & 1;
    const int wn   = wid >> 1;
    const int m0   = blockIdx.y * 128;
    const int n0   = blockIdx.x * 128;

    const uint32_t bAh = smem_u32(sAh);
    const uint32_t bAl = smem_u32(sAl);
    const uint32_t bBh = smem_u32(sBh);
    const uint32_t bBl = smem_u32(sBl);

    float acc[4][4][4] = {};

    for (int kc = 0; kc < KIN / 32; ++kc) {
        #pragma unroll
        for (int i = 0; i < 2; ++i) {
            int lin = i * 256 + tid;
            int r = lin >> 2, c4 = lin & 3;
            size_t go = (size_t)r * KIN + kc * 32 + c4 * 8;
            int so = r * SSTR + c4 * 8;
            *(uint4*)(sAh + so) = *(const uint4*)(g_xh + (size_t)m0 * KIN + go);
            *(uint4*)(sAl + so) = *(const uint4*)(g_xl + (size_t)m0 * KIN + go);
            *(uint4*)(sBh + so) = *(const uint4*)(g_wh + (size_t)n0 * KIN + go);
            *(uint4*)(sBl + so) = *(const uint4*)(g_wl + (size_t)n0 * KIN + go);
        }
        __syncthreads();

        #pragma unroll
        for (int kk = 0; kk < 2; ++kk) {
            uint32_t ah[4][4], al[4][4], bh[2][4], bl[2][4];
            #pragma unroll
            for (int mt = 0; mt < 4; ++mt) {
                uint32_t off = (uint32_t)((wm * 64 + mt * 16 + (lane & 15)) * SSTR
                                          + kk * 16 + (lane >> 4) * 8) * 2;
                ldsm_x4(ah[mt], bAh + off);
                ldsm_x4(al[mt], bAl + off);
            }
            #pragma unroll
            for (int ntp = 0; ntp < 2; ++ntp) {
                uint32_t off = (uint32_t)((wn * 32 + ntp * 16 + ((lane >> 4) * 8) + (lane & 7)) * SSTR
                                          + kk * 16 + ((lane >> 3) & 1) * 8) * 2;
                ldsm_x4(bh[ntp], bBh + off);
                ldsm_x4(bl[ntp], bBl + off);
            }
            #pragma unroll
            for (int mt = 0; mt < 4; ++mt)
                #pragma unroll
                for (int nf = 0; nf < 4; ++nf) {
                    uint32_t bh0 = bh[nf >> 1][(nf & 1) * 2], bh1 = bh[nf >> 1][(nf & 1) * 2 + 1];
                    uint32_t bl0 = bl[nf >> 1][(nf & 1) * 2], bl1 = bl[nf >> 1][(nf & 1) * 2 + 1];
                    mma_bf16(acc[mt][nf], ah[mt], bh0, bh1);
                    mma_bf16(acc[mt][nf], ah[mt], bl0, bl1);
                    mma_bf16(acc[mt][nf], al[mt], bh0, bh1);
                }
        }
        __syncthreads();
    }

    #pragma unroll
    for (int mt = 0; mt < 4; ++mt)
        #pragma unroll
        for (int nf = 0; nf < 4; ++nf) {
            int row0 = m0 + wm * 64 + mt * 16 + (lane >> 2);
            int col  = n0 + wn * 32 + nf * 8 + (lane & 3) * 2;
            *(float2*)&g_h[(size_t)row0 * OUTD + col] =
                make_float2(acc[mt][nf][0], acc[mt][nf][1]);
            *(float2*)&g_h[(size_t)(row0 + 8) * OUTD + col] =
                make_float2(acc[mt][nf][2], acc[mt][nf][3]);
        }
}

// ==================== s1, s2 ====================
__global__ void s12_kernel(const float* __restrict__ a1, const float* __restrict__ a2) {
    int i = blockIdx.x;
    int k = threadIdx.x;
    float h = g_h[(size_t)i * OUTD + k];
    float v1 = h * a1[k];
    float v2 = h * a2[k];
    #pragma unroll
    for (int o = 16; o; o >>= 1) {
        v1 += __shfl_down_sync(0xFFFFFFFFu, v1, o);
        v2 += __shfl_down_sync(0xFFFFFFFFu, v2, o);
    }
    __shared__ float r1[8], r2[8];
    if ((k & 31) == 0) { r1[k >> 5] = v1; r2[k >> 5] = v2; }
    __syncthreads();
    if (k < 8) {
        v1 = r1[k]; v2 = r2[k];
        #pragma unroll
        for (int o = 4; o; o >>= 1) {
            v1 += __shfl_down_sync(0xFFu, v1, o);
            v2 += __shfl_down_sync(0xFFu, v2, o);
        }
        if (k == 0) { g_key[i] = v1; g_s2[i] = v2; }
    }
}

// ==================== 8-CTA cluster bitonic sort ====================
#define CLUSTER_SYNC() do {                                             \
    asm volatile("barrier.cluster.arrive.aligned;" ::: "memory");       \
    asm volatile("barrier.cluster.wait.aligned;" ::: "memory");         \
} while (0)

__device__ __forceinline__ unsigned long long dsmem_ld64(uint32_t laddr, uint32_t rank) {
    uint32_t ra;
    unsigned long long v;
    asm volatile("mapa.shared::cluster.u32 %0, %1, %2;" : "=r"(ra) : "r"(laddr), "r"(rank));
    asm volatile("ld.shared::cluster.u64 %0, [%1];" : "=l"(v) : "r"(ra) : "memory");
    return v;
}
__device__ __forceinline__ unsigned long long u64min(unsigned long long a, unsigned long long b) { return a < b ? a : b; }
__device__ __forceinline__ unsigned long long u64max(unsigned long long a, unsigned long long b) { return a < b ? b : a; }

__global__ void __launch_bounds__(1024, 1) __cluster_dims__(8, 1, 1) sort_kernel() {
    __shared__ unsigned long long s[1024];
    const int t = threadIdx.x;
    uint32_t rank;
    asm("mov.u32 %0, %%cluster_ctarank;" : "=r"(rank));
    const int ge = (int)rank * 1024 + t;

    uint32_t u = __float_as_uint(g_key[ge]);
    u ^= (u & 0x80000000u) ? 0xFFFFFFFFu : 0x80000000u;
    unsigned long long own = ((unsigned long long)u << 13) | (unsigned)ge;

    // sizes 2..32: pure shuffles (strides 1..16 pair lanes)
    #pragma unroll
    for (int size = 2; size <= 32; size <<= 1) {
        bool up = ((ge & size) == 0);
        #pragma unroll
        for (int stride = size >> 1; stride >= 1; stride >>= 1) {
            unsigned long long p = __shfl_xor_sync(0xFFFFFFFFu, own, stride);
            bool keepmin = (((t & stride) == 0) == up);
            own = keepmin ? u64min(own, p) : u64max(own, p);
        }
    }
    s[t] = own;
    __syncthreads();

    // sizes 64..1024: smem strides 32..512, shuffles below
    for (int size = 64; size <= 1024; size <<= 1) {
        for (int stride = size >> 1; stride >= 32; stride >>= 1) {
            if (t < 512) {
                int a = ((t & ~(stride - 1)) << 1) | (t & (stride - 1));
                int b = a + stride;
                bool up = ((((int)rank * 1024 + a) & size) == 0);
                unsigned long long x = s[a], y = s[b];
                if ((x > y) == up) { s[a] = y; s[b] = x; }
            }
            __syncthreads();
        }
        own = s[t];
        bool up = ((ge & size) == 0);
        #pragma unroll
        for (int stride = 16; stride >= 1; stride >>= 1) {
            unsigned long long p = __shfl_xor_sync(0xFFFFFFFFu, own, stride);
            bool keepmin = (((t & stride) == 0) == up);
            own = keepmin ? u64min(own, p) : u64max(own, p);
        }
        s[t] = own;
        __syncthreads();
    }

    CLUSTER_SYNC();

    const uint32_t myaddr = smem_u32(&s[t]);
    for (int size = 2048; size <= 8192; size <<= 1) {
        bool up = ((ge & size) == 0);
        for (int stride = size >> 1; stride >= 1024; stride >>= 1) {
            unsigned long long mine = s[t];
            unsigned long long other = dsmem_ld64(myaddr, rank ^ (uint32_t)(stride >> 10));
            bool keepmin = (((ge & stride) == 0) == up);
            unsigned long long nv = keepmin ? u64min(mine, other) : u64max(mine, other);
            CLUSTER_SYNC();
            s[t] = nv;
            CLUSTER_SYNC();
        }
        for (int stride = 512; stride >= 32; stride >>= 1) {
            if (t < 512) {
                int a = ((t & ~(stride - 1)) << 1) | (t & (stride - 1));
                int b = a + stride;
                unsigned long long x = s[a], y = s[b];
                if ((x > y) == up) { s[a] = y; s[b] = x; }
            }
            __syncthreads();
        }
        own = s[t];
        #pragma unroll
        for (int stride = 16; stride >= 1; stride >>= 1) {
            unsigned long long p = __shfl_xor_sync(0xFFFFFFFFu, own, stride);
            bool keepmin = (((t & stride) == 0) == up);
            own = keepmin ? u64min(own, p) : u64max(own, p);
        }
        s[t] = own;
        __syncthreads();
        CLUSTER_SYNC();
    }

    int idx = (int)(own & 0x1FFFu);
    uint32_t uu = (uint32_t)(own >> 13);
    uu ^= (uu & 0x80000000u) ? 0x80000000u : 0xFFFFFFFFu;
    g_key[ge] = __uint_as_float(uu);
    g_idx[ge] = idx;
}

// ==================== pass 1: per-chunk weighted sums (transposed out) ====================
__global__ void chunksum_kernel() {
    int c = blockIdx.x;
    int k = threadIdx.x;
    if (k >= W257) return;
    float m1 = g_key[N - 1];
    float acc1 = 0.f, acc2 = 0.f;
    #pragma unroll 4
    for (int r = 0; r < CHL; ++r) {
        int p = c * CHL + r;
        float d = g_key[p] - m1;
        float w1 = __expf(d);
        float w2 = __expf(LRELU_ALPHA * d);
        float v = (k < OUTD) ? g_h[(size_t)g_idx[p] * OUTD + k] : 1.0f;
        acc1 += w1 * v;
        acc2 += w2 * v;
    }
    g_cs1[k * NCH + c] = acc1;
    g_cs2[k * NCH + c] = acc2;
}

// ==================== pass 2: parallel chunk-offset scans ====================
__global__ void chunkscan_kernel() {      // grid = W257 blocks, 512 threads
    int k = blockIdx.x;
    int t = threadIdx.x;
    int lane = t & 31, w = t >> 5;
    float a = g_cs2[k * NCH + t];                 // forward (alpha branch)
    float b = g_cs1[k * NCH + (NCH - 1 - t)];     // reversed (exp branch)
    float ia = a, ib = b;
    #pragma unroll
    for (int o = 1; o < 32; o <<= 1) {
        float pa = __shfl_up_sync(0xFFFFFFFFu, ia, o);
        float pb = __shfl_up_sync(0xFFFFFFFFu, ib, o);
        if (lane >= o) { ia += pa; ib += pb; }
    }
    __shared__ float wa[16], wb[16];
    if (lane == 31) { wa[w] = ia; wb[w] = ib; }
    __syncthreads();
    if (t < 16) {
        float xa = wa[t], xb = wb[t];
        #pragma unroll
        for (int o = 1; o < 16; o <<= 1) {
            float pa = __shfl_up_sync(0xFFFFu, xa, o);
            float pb = __shfl_up_sync(0xFFFFu, xb, o);
            if (t >= o) { xa += pa; xb += pb; }
        }
        wa[t] = xa; wb[t] = xb;
    }
    __syncthreads();
    float offa = w ? wa[w - 1] : 0.f;
    float offb = w ? wb[w - 1] : 0.f;
    g_co2[k * NCH + t]             = ia - a + offa;   // exclusive prefix
    g_co1[k * NCH + (NCH - 1 - t)] = ib - b + offb;   // exclusive suffix
}

// ==================== pass 3: full prefix/suffix arrays ====================
__global__ void writescan_kernel() {
    int c = blockIdx.x;
    int k = threadIdx.x;
    if (k >= W257) return;
    float m1 = g_key[N - 1];

    float acc = g_co2[k * NCH + c];
    #pragma unroll 4
    for (int r = 0; r < CHL; ++r) {
        int p = c * CHL + r;
        g_P2[(size_t)p * W257 + k] = acc;
        float v = (k < OUTD) ? g_h[(size_t)g_idx[p] * OUTD + k] : 1.0f;
        acc += __expf(LRELU_ALPHA * (g_key[p] - m1)) * v;
    }
    if (c == NCH - 1) g_P2[(size_t)N * W257 + k] = acc;

    acc = g_co1[k * NCH + c];
    #pragma unroll 4
    for (int r = CHL - 1; r >= 0; --r) {
        int p = c * CHL + r;
        float v = (k < OUTD) ? g_h[(size_t)g_idx[p] * OUTD + k] : 1.0f;
        acc += __expf(g_key[p] - m1) * v;
        g_SE[(size_t)p * W257 + k] = acc;
    }
    if (c == NCH - 1) g_SE[(size_t)N * W257 + k] = 0.f;
}

// ==================== epilogue ====================
__global__ void out_kernel(float* __restrict__ out) {
    int i = blockIdx.x;
    int k = threadIdx.x;
    __shared__ int   sp;
    __shared__ float sr;
    if (k == 0) {
        float m1 = g_key[N - 1];
        float s2 = g_s2[i];
        float t = -s2;
        int lo = 0, hi = N;
        while (lo < hi) {
            int mid = (lo + hi) >> 1;
            if (g_key[mid] > t) hi = mid; else lo = mid + 1;
        }
        sp = lo;
        sr = __expf((LRELU_ALPHA - 1.0f) * (s2 + m1));
    }
    __syncthreads();
    size_t basep = (size_t)sp * W257;
    float r = sr;
    float den = g_SE[basep + OUTD] + r * g_P2[basep + OUTD];
    float num = g_SE[basep + k]    + r * g_P2[basep + k];
    out[(size_t)i * OUTD + k] = num / den;
}

// ==================== launch ====================
extern "C" void kernel_launch(void* const* d_in, const int* in_sizes, int n_in,
                              void* d_out, int out_size) {
    const float* x  = (const float*)d_in[0];
    const float* Wm = (const float*)d_in[2];
    const float* a1 = (const float*)d_in[3];
    const float* a2 = (const float*)d_in[4];
    float* out = (float*)d_out;

    int pairs = (N * KIN + OUTD * KIN) / 2;
    convert_kernel<<<(pairs + 255) / 256, 256>>>(x, Wm);

    gemm_tc_kernel<<<dim3(OUTD / 128, N / 128), 256>>>();

    s12_kernel<<<N, 256>>>(a1, a2);

    sort_kernel<<<8, 1024>>>();

    chunksum_kernel<<<NCH, 288>>>();
    chunkscan_kernel<<<W257, 512>>>();
    writescan_kernel<<<NCH, 288>>>();
    out_kernel<<<N, 256>>>(out);
}